// round 7
// baseline (speedup 1.0000x reference)
#include <cuda_runtime.h>
#include <cstdint>

// KNN: B=4, N=8192, D=16, K=16. Output [B, N, K] neighbor indices,
// ascending distance, ties -> lower index (matches jax.lax.top_k).
//
// KEY FIX (R6): output dtype is float32 — the harness canonicalizes the
// reference int indices to f32. Previous rounds wrote int32 bit patterns,
// which reinterpret as denormals (~0) -> rel_err exactly 1.0.

#define BATCH 4
#define NPTS  8192
#define DIM   16
#define KSEL  16
#define TJ    256
#define NTILES (NPTS / TJ)
#define THREADS 256
#define X_ELEMS (BATCH * NPTS * DIM)

__global__ void __launch_bounds__(THREADS)
knn_kernel(const float* __restrict__ x, float* __restrict__ out) {
    __shared__ float s_pts[TJ * DIM];   // 16 KB
    __shared__ float s_nrm[TJ];         //  1 KB

    const int tid  = threadIdx.x;
    const int grow = blockIdx.x * THREADS + tid;   // global row 0..32767
    const int batch = grow >> 13;                  // / 8192
    const int row   = grow & (NPTS - 1);

    const float* xb = x + (size_t)batch * NPTS * DIM;

    // query into registers + own norm (separate mul + sequential adds)
    float q[DIM];
#pragma unroll
    for (int k = 0; k < DIM; ++k)
        q[k] = xb[(size_t)row * DIM + k];
    float ni = __fmul_rn(q[0], q[0]);
#pragma unroll
    for (int k = 1; k < DIM; ++k)
        ni = __fadd_rn(ni, __fmul_rn(q[k], q[k]));

    // selection lists: sorted ascending by (distance, index)
    float d[KSEL];
    int   id[KSEL];
#pragma unroll
    for (int t = 0; t < KSEL; ++t) { d[t] = __int_as_float(0x7F800000); id[t] = 0; }

    for (int tile = 0; tile < NTILES; ++tile) {
        const int jbase = tile * TJ;

        // cooperative coalesced tile load
        {
            const float4* src = (const float4*)(xb + (size_t)jbase * DIM);
            float4* dst = (float4*)s_pts;
#pragma unroll
            for (int v = 0; v < TJ * DIM / 4 / THREADS; ++v)
                dst[tid + v * THREADS] = src[tid + v * THREADS];
        }
        __syncthreads();

        // tile norms: one point per thread
        {
            const float* p = s_pts + tid * DIM;
            float s = __fmul_rn(p[0], p[0]);
#pragma unroll
            for (int k = 1; k < DIM; ++k)
                s = __fadd_rn(s, __fmul_rn(p[k], p[k]));
            s_nrm[tid] = s;
        }
        __syncthreads();

        // scan: every thread walks the same jl -> broadcast smem reads
        for (int jl = 0; jl < TJ; ++jl) {
            const float* p = s_pts + jl * DIM;
            float dot = __fmul_rn(q[0], p[0]);
#pragma unroll
            for (int k = 1; k < DIM; ++k)
                dot = __fmaf_rn(q[k], p[k], dot);
            float t1   = __fadd_rn(ni, __fmul_rn(-2.0f, dot));
            float dist = __fadd_rn(t1, s_nrm[jl]);

            if (dist < d[KSEL - 1]) {              // strict: ties keep earlier j
                d[KSEL - 1]  = dist;
                id[KSEL - 1] = jbase + jl;
#pragma unroll
                for (int t = KSEL - 1; t > 0; --t) {
                    if (d[t] < d[t - 1]) {
                        float tf = d[t - 1];  d[t - 1]  = d[t];  d[t]  = tf;
                        int   ti = id[t - 1]; id[t - 1] = id[t]; id[t] = ti;
                    }
                }
            }
        }
        __syncthreads();
    }

    float* op = out + (size_t)grow * KSEL;
#pragma unroll
    for (int t = 0; t < KSEL; ++t)
        op[t] = (float)id[t];                      // FLOAT output (the fix)
}

extern "C" void kernel_launch(void* const* d_in, const int* in_sizes, int n_in,
                              void* d_out, int out_size) {
    // order-agnostic input binding (elements or bytes)
    const float* x = nullptr;
    for (int i = 0; i < n_in; ++i)
        if (in_sizes[i] == X_ELEMS) { x = (const float*)d_in[i]; break; }
    if (!x)
        for (int i = 0; i < n_in; ++i)
            if (in_sizes[i] == X_ELEMS * 4) { x = (const float*)d_in[i]; break; }
    if (!x) {
        int best = 0;
        for (int i = 1; i < n_in; ++i)
            if (in_sizes[i] > in_sizes[best]) best = i;
        x = (const float*)d_in[best];
    }
    knn_kernel<<<BATCH * NPTS / THREADS, THREADS>>>(x, (float*)d_out);
}